// round 3
// baseline (speedup 1.0000x reference)
#include <cuda_runtime.h>

#define NEG_INF __int_as_float(0xff800000)

#define XS 34              // smem img row stride (floats)
#define CSTRIDE (6*XS)     // 204 floats per channel tile (6 rows: y0-1 .. y0+4)

// Block: 128 threads = 32 x-lanes x 4 y-rows.
// Each thread computes 4 consecutive o-channels (og*4 .. og*4+3) for ONE (y,x).
// Grid: (og=8, ytile=8, b=8) = 512 blocks x 4 warps = 2048 warps (~13.8/SM).
__global__ __launch_bounds__(128)
void bconv_kernel(const float* __restrict__ img,
                  const float* __restrict__ ker,
                  float* __restrict__ out)
{
    __shared__ float simg[32 * CSTRIDE];     // 26112 B: 32 c x 6 rows x 34 cols (-inf pad)
    __shared__ float sker[32 * 9 * 4];       // 4608 B: [c][p][j] -> float4 per (c,p)

    const int og  = blockIdx.x;              // 0..7  (group of 4 output channels)
    const int yt  = blockIdx.y;              // 0..7
    const int b   = blockIdx.z;              // 0..7
    const int tid = threadIdx.x;
    const int x   = tid & 31;
    const int ty  = tid >> 5;                // 0..3  (local y row)
    const int y0  = yt * 4;
    const int ob  = og * 4;

    // ---- image tile: rows y0-1 .. y0+4, cols -1..32, -inf OOB ----
    const float* gimg = img + b * 32 * 32 * 32;
    for (int idx = tid; idx < 32 * CSTRIDE; idx += 128) {
        int c   = idx / CSTRIDE;
        int rem = idx - c * CSTRIDE;
        int r   = rem / XS;
        int xx  = rem - r * XS;
        int h   = y0 - 1 + r;
        int w   = xx - 1;
        float v = NEG_INF;
        if ((unsigned)h < 32u && (unsigned)w < 32u)
            v = gimg[(c * 32 + h) * 32 + w];
        simg[idx] = v;
    }

    // ---- flipped kernel slice: sker[c*36 + p*4 + j] = ker[ob+j][c][2-dy][2-dx] ----
    for (int idx = tid; idx < 32 * 36; idx += 128) {
        int c   = idx / 36;
        int rem = idx - c * 36;
        int p   = rem >> 2;
        int j   = rem & 3;
        int dy  = p / 3, dx = p - dy * 3;
        sker[idx] = ker[(((ob + j) * 32 + c) * 3 + (2 - dy)) * 3 + (2 - dx)];
    }
    __syncthreads();

    float4 acc = make_float4(NEG_INF, NEG_INF, NEG_INF, NEG_INF);
    const float4* sk4 = (const float4*)sker;   // index: c*9 + p (block-uniform -> broadcast)

    for (int c = 0; c < 32; c++) {
        // 9 image values around (y,x): tile rows ty..ty+2 (global y-1..y+1)
        const float* ip = simg + c * CSTRIDE + ty * XS + x;
        float v[3][3];
#pragma unroll
        for (int r = 0; r < 3; r++) {
#pragma unroll
            for (int d = 0; d < 3; d++) v[r][d] = ip[r * XS + d];
        }
#pragma unroll
        for (int p = 0; p < 9; p++) {
            const float4 k = sk4[c * 9 + p];
            const float vv = v[p / 3][p % 3];
            acc.x = fmaxf(acc.x, vv + k.x);
            acc.y = fmaxf(acc.y, vv + k.y);
            acc.z = fmaxf(acc.z, vv + k.z);
            acc.w = fmaxf(acc.w, vv + k.w);
        }
    }

    // ---- store 4 o-channels ----
    float* gout = out + ((b * 32 + ob) * 32 + (y0 + ty)) * 32 + x;
    gout[0 * 1024] = acc.x;
    gout[1 * 1024] = acc.y;
    gout[2 * 1024] = acc.z;
    gout[3 * 1024] = acc.w;
}

extern "C" void kernel_launch(void* const* d_in, const int* in_sizes, int n_in,
                              void* d_out, int out_size)
{
    const float* img = (const float*)d_in[0];
    const float* ker = (const float*)d_in[1];
    float*       out = (float*)d_out;
    dim3 grid(8, 8, 8);   // (o-group, ytile, batch)
    bconv_kernel<<<grid, 128>>>(img, ker, out);
}

// round 4
// speedup vs baseline: 1.0153x; 1.0153x over previous
#include <cuda_runtime.h>

#define NEG_INF __int_as_float(0xff800000)

// Block: 256 threads = 32 x-lanes x 8 y-rows. Each thread: 2 o-channels, 1 (y,x).
// Grid: (o-pair=16, ytile=4, b=8) = 512 blocks x 8 warps = 4096 warps (~27.7/SM).
// smem img paired by channel: [c2=16][row=10][x=34][2] -> one LDS.64 feeds 2 channels.
// smem ker packed float4 per (c2,p): (o0c0, o1c0, o0c1, o1c1).
__global__ __launch_bounds__(256)
void bconv_kernel(const float* __restrict__ img,
                  const float* __restrict__ ker,
                  float* __restrict__ out)
{
    __shared__ float2 simg[16 * 10 * 34];   // 43520 B
    __shared__ float4 sker[16 * 9];         //  2304 B

    const int o2  = blockIdx.x;             // 0..15 (pair of output channels)
    const int yt  = blockIdx.y;             // 0..3
    const int b   = blockIdx.z;             // 0..7
    const int tid = threadIdx.x;
    const int x   = tid & 31;
    const int ty  = tid >> 5;               // 0..7
    const int y0  = yt * 8;

    // ---- image tile: [c2][r][xx] with r -> global h = y0-1+r, xx -> w = xx-1 ----
    const float* gimg = img + b * 32 * 32 * 32;
    for (int i = tid; i < 16 * 10 * 34; i += 256) {
        int c2  = i / 340;
        int rem = i - c2 * 340;
        int r   = rem / 34;
        int xx  = rem - r * 34;
        int h   = y0 - 1 + r;
        int w   = xx - 1;
        float2 v = make_float2(NEG_INF, NEG_INF);
        if ((unsigned)h < 32u && (unsigned)w < 32u) {
            const float* p = gimg + ((c2 * 2) * 32 + h) * 32 + w;
            v.x = p[0];
            v.y = p[1024];                  // channel c2*2+1
        }
        simg[i] = v;
    }

    // ---- kernel slice: sker[c2*9+p] = (k[o0][c0][P], k[o1][c0][P], k[o0][c1][P], k[o1][c1][P])
    //      with P = (2-dy, 2-dx), p = dy*3+dx ----
    if (tid < 144) {
        int c2 = tid / 9;
        int p  = tid - c2 * 9;
        int dy = p / 3, dx = p - dy * 3;
        int c0 = c2 * 2;
        int o0 = o2 * 2;
        int off = (2 - dy) * 3 + (2 - dx);
        const float* kb = ker + off;
        float4 k;
        k.x = kb[((o0)     * 32 + c0)     * 9];
        k.y = kb[((o0 + 1) * 32 + c0)     * 9];
        k.z = kb[((o0)     * 32 + c0 + 1) * 9];
        k.w = kb[((o0 + 1) * 32 + c0 + 1) * 9];
        sker[tid] = k;
    }
    __syncthreads();

    float acc0 = NEG_INF, acc1 = NEG_INF;

    // per-thread base: rows ty..ty+2 of tile (global y-1..y+1), cols x..x+2
    const float2* vbase = simg + ty * 34 + x;

#pragma unroll 1
    for (int c2 = 0; c2 < 16; c2++) {
        const float2* vp = vbase + c2 * 340;
        float2 v[3][3];
#pragma unroll
        for (int r = 0; r < 3; r++) {
#pragma unroll
            for (int d = 0; d < 3; d++) v[r][d] = vp[r * 34 + d];
        }
#pragma unroll
        for (int p = 0; p < 9; p++) {
            const float4 k = sker[c2 * 9 + p];
            const float2 vv = v[p / 3][p % 3];
            acc0 = fmaxf(acc0, vv.x + k.x);
            acc1 = fmaxf(acc1, vv.x + k.y);
            acc0 = fmaxf(acc0, vv.y + k.z);
            acc1 = fmaxf(acc1, vv.y + k.w);
        }
    }

    // ---- store 2 o-channels ----
    float* gout = out + ((b * 32 + o2 * 2) * 32 + (y0 + ty)) * 32 + x;
    gout[0]    = acc0;
    gout[1024] = acc1;
}

extern "C" void kernel_launch(void* const* d_in, const int* in_sizes, int n_in,
                              void* d_out, int out_size)
{
    const float* img = (const float*)d_in[0];
    const float* ker = (const float*)d_in[1];
    float*       out = (float*)d_out;
    dim3 grid(16, 4, 8);   // (o-pair, ytile, batch)
    bconv_kernel<<<grid, 256>>>(img, ker, out);
}

// round 5
// speedup vs baseline: 1.2718x; 1.2527x over previous
#include <cuda_runtime.h>
#include <cuda_fp16.h>

#define NEG_INF __int_as_float(0xff800000)

// fp16x2 max-plus conv.
// Block: 256 threads = 32 x-lanes x 8 y-rows. Thread: 2 o-channels, 1 (y,x).
// Grid: (o-pair=16, ytile=4, b=8) = 512 blocks x 8 warps = 4096 warps.
// smem img: half2 channel pairs [c2=16][row=10][x=34].
// smem ker: per (c2,p) a float2 = { half2(k[o0][2c2],k[o0][2c2+1]), half2(k[o1][...]) }.
__global__ __launch_bounds__(256)
void bconv_kernel(const float* __restrict__ img,
                  const float* __restrict__ ker,
                  float* __restrict__ out)
{
    __shared__ __half2 simg[16 * 10 * 34];   // 21760 B
    __shared__ float2  sker[16 * 9];         //  1152 B (each float2 = two half2)

    const int o2  = blockIdx.x;              // 0..15 (pair of output channels)
    const int yt  = blockIdx.y;              // 0..3
    const int b   = blockIdx.z;              // 0..7
    const int tid = threadIdx.x;
    const int x   = tid & 31;
    const int ty  = tid >> 5;                // 0..7
    const int y0  = yt * 8;

    // ---- image tile -> half2(c,c+1), rows y0-1..y0+4? (10 rows: y0-1..y0+8), cols -1..32 ----
    const float* gimg = img + b * 32 * 32 * 32;
    for (int i = tid; i < 16 * 10 * 34; i += 256) {
        int c2  = i / 340;
        int rem = i - c2 * 340;
        int r   = rem / 34;
        int xx  = rem - r * 34;
        int h   = y0 - 1 + r;
        int w   = xx - 1;
        float vx = NEG_INF, vy = NEG_INF;
        if ((unsigned)h < 32u && (unsigned)w < 32u) {
            const float* p = gimg + ((c2 * 2) * 32 + h) * 32 + w;
            vx = p[0];
            vy = p[1024];                    // channel 2*c2+1
        }
        simg[i] = __floats2half2_rn(vx, vy);
    }

    // ---- kernel slice: sker[c2*9+p] = { h2(k[o0][c0][P], k[o0][c1][P]), h2(k[o1][c0][P], k[o1][c1][P]) }
    //      P = (2-dy,2-dx), p = dy*3+dx ----
    if (tid < 144) {
        int c2 = tid / 9;
        int p  = tid - c2 * 9;
        int dy = p / 3, dx = p - dy * 3;
        int c0 = c2 * 2;
        int o0 = o2 * 2;
        const float* kb = ker + (2 - dy) * 3 + (2 - dx);
        __half2 ka = __floats2half2_rn(kb[((o0)     * 32 + c0) * 9],
                                       kb[((o0)     * 32 + c0 + 1) * 9]);
        __half2 kc = __floats2half2_rn(kb[((o0 + 1) * 32 + c0) * 9],
                                       kb[((o0 + 1) * 32 + c0 + 1) * 9]);
        float2 kk;
        kk.x = __uint_as_float(*(const unsigned int*)&ka);
        kk.y = __uint_as_float(*(const unsigned int*)&kc);
        sker[tid] = kk;
    }
    __syncthreads();

    const __half2 ninf2 = __floats2half2_rn(NEG_INF, NEG_INF);
    __half2 acc0 = ninf2, acc1 = ninf2;

    // thread's window: tile rows ty..ty+2 (global y-1..y+1), cols x..x+2
    const __half2* vbase = simg + ty * 34 + x;

#pragma unroll 1
    for (int c2 = 0; c2 < 16; c2++) {
        const __half2* vp = vbase + c2 * 340;
        __half2 v[9];
#pragma unroll
        for (int r = 0; r < 3; r++) {
#pragma unroll
            for (int d = 0; d < 3; d++) v[r * 3 + d] = vp[r * 34 + d];
        }
#pragma unroll
        for (int p = 0; p < 9; p++) {
            const float2 kk = sker[c2 * 9 + p];
            unsigned ua = __float_as_uint(kk.x);
            unsigned ub = __float_as_uint(kk.y);
            __half2 ka = *(__half2*)&ua;
            __half2 kb2 = *(__half2*)&ub;
            acc0 = __hmax2(acc0, __hadd2(v[p], ka));
            acc1 = __hmax2(acc1, __hadd2(v[p], kb2));
        }
    }

    // ---- reduce channel-pair halves, store 2 o-channels in fp32 ----
    float r0 = fmaxf(__low2float(acc0), __high2float(acc0));
    float r1 = fmaxf(__low2float(acc1), __high2float(acc1));

    float* gout = out + ((b * 32 + o2 * 2) * 32 + (y0 + ty)) * 32 + x;
    gout[0]    = r0;
    gout[1024] = r1;
}

extern "C" void kernel_launch(void* const* d_in, const int* in_sizes, int n_in,
                              void* d_out, int out_size)
{
    const float* img = (const float*)d_in[0];
    const float* ker = (const float*)d_in[1];
    float*       out = (float*)d_out;
    dim3 grid(16, 4, 8);   // (o-pair, ytile, batch)
    bconv_kernel<<<grid, 256>>>(img, ker, out);
}